// round 13
// baseline (speedup 1.0000x reference)
#include <cuda_runtime.h>
#include <cuda_fp16.h>
#include <math.h>
#include <stdint.h>

// ---------------- problem constants ----------------
#define BATCH     32768
#define DIM       128
#define NCENT     6400
#define KC        64
#define AMT       (BATCH / 16)     // 2048 A row-tiles (m16)
#define BNT       (NCENT / 8)      // 800  B col-tiles (n8)
#define NCHUNKS   50               // chunk = 16 n8-tiles (128 centers)
#define NUNITS    (512 * NCHUNKS)  // 25600 single-chunk units
#define NGRP      400              // 16-center groups
#define GRID_SW   444              // 148 SMs x occ 3

// ---------------- device scratch ----------------
__device__ uint4 g_afrag[AMT][8][32];      // 8.4 MB (fp16 main plane, A frag)
__device__ uint4 g_bfrag[BNT][4][32];      // 1.6 MB (fp16 main plane, B frag, kt-pair)
__device__ float g_c2[NCENT];
__device__ float g_x2[BATCH];
__device__ float g_xb2[BATCH];             // ||x - fp16(x)||^2
__device__ __half g_smin16[BATCH][NGRP];   // 26 MB: per (row, 16-group) min, rounded DOWN
__device__ int   g_t1;
__device__ unsigned g_mc2e, g_mcb2e;       // enc(max c2), enc(max ||c_res||^2); idempotent

// ---------------- helpers ----------------
__device__ __forceinline__ uint32_t packh(float lo, float hi) {
    __half2 h = __floats2half2_rn(lo, hi);
    return *reinterpret_cast<uint32_t*>(&h);
}
__device__ __forceinline__ float h16(float v) { return __half2float(__float2half_rn(v)); }
__device__ __forceinline__ uint32_t encf(float f) {
    uint32_t u = __float_as_uint(f);
    return (u & 0x80000000u) ? ~u : (u | 0x80000000u);
}
__device__ __forceinline__ float decf(uint32_t e) {
    uint32_t u = (e & 0x80000000u) ? (e ^ 0x80000000u) : ~e;
    return __uint_as_float(u);
}
__device__ __forceinline__ void mma16816(float* d, const uint4& a,
                                         uint32_t b0, uint32_t b1) {
    asm volatile(
        "mma.sync.aligned.m16n8k16.row.col.f32.f16.f16.f32 "
        "{%0,%1,%2,%3}, {%4,%5,%6,%7}, {%8,%9}, {%0,%1,%2,%3};"
        : "+f"(d[0]), "+f"(d[1]), "+f"(d[2]), "+f"(d[3])
        : "r"(a.x), "r"(a.y), "r"(a.z), "r"(a.w), "r"(b0), "r"(b1));
}

// ---------------------------------------------------------------------------
// merged prep: warps [0, BATCH) -> x rows; warps [BATCH, BATCH+NCENT) -> centers
// ---------------------------------------------------------------------------
__global__ void prep_kernel(const float* __restrict__ x,
                            const float* __restrict__ centers) {
    int warp = (blockIdx.x * blockDim.x + threadIdx.x) >> 5;
    int lane = threadIdx.x & 31;

    if (warp < BATCH) {
        int r = warp;
        int M = r >> 4, g = r & 15;
        int kt = lane >> 2, t = lane & 3;
        const float* row = x + (size_t)r * DIM;
        float2 lo = *reinterpret_cast<const float2*>(row + kt * 16 + 2 * t);
        float2 hi = *reinterpret_cast<const float2*>(row + kt * 16 + 8 + 2 * t);

        float r0 = lo.x - h16(lo.x), r1 = lo.y - h16(lo.y);
        float r2 = hi.x - h16(hi.x), r3 = hi.y - h16(hi.y);
        float s  = lo.x * lo.x + lo.y * lo.y + hi.x * hi.x + hi.y * hi.y;
        float sb = r0 * r0 + r1 * r1 + r2 * r2 + r3 * r3;
#pragma unroll
        for (int off = 16; off > 0; off >>= 1) {
            s  += __shfl_xor_sync(0xFFFFFFFFu, s, off);
            sb += __shfl_xor_sync(0xFFFFFFFFu, sb, off);
        }
        if (lane == 0) { g_x2[r] = s; g_xb2[r] = sb; }
        if (warp == 0 && lane == 1) g_t1 = 0;

        uint32_t w0 = packh(lo.x, lo.y);
        uint32_t w1 = packh(hi.x, hi.y);
        uint32_t* base = reinterpret_cast<uint32_t*>(&g_afrag[M][kt][(g & 7) * 4 + t]);
        if (g < 8) { base[0] = w0; base[2] = w1; }
        else       { base[1] = w0; base[3] = w1; }
    } else if (warp < BATCH + NCENT) {
        int n = warp - BATCH;
        int N = n >> 3, g = n & 7;
        int j = lane & 15;
        int kt2 = j >> 2, t = j & 3;
        const float* row = centers + (size_t)n * DIM;
        int c0 = kt2 * 32 + 2 * t;
        float2 e0, e1, o0, o1;
        float s = 0.0f, sb = 0.0f;
        if (lane < 16) {
            e0 = *reinterpret_cast<const float2*>(row + c0);
            e1 = *reinterpret_cast<const float2*>(row + c0 + 8);
            o0 = *reinterpret_cast<const float2*>(row + c0 + 16);
            o1 = *reinterpret_cast<const float2*>(row + c0 + 24);
            float q0 = e0.x - h16(e0.x), q1 = e0.y - h16(e0.y);
            float q2 = e1.x - h16(e1.x), q3 = e1.y - h16(e1.y);
            float q4 = o0.x - h16(o0.x), q5 = o0.y - h16(o0.y);
            float q6 = o1.x - h16(o1.x), q7 = o1.y - h16(o1.y);
            s  = e0.x*e0.x + e0.y*e0.y + e1.x*e1.x + e1.y*e1.y
               + o0.x*o0.x + o0.y*o0.y + o1.x*o1.x + o1.y*o1.y;
            sb = q0*q0 + q1*q1 + q2*q2 + q3*q3 + q4*q4 + q5*q5 + q6*q6 + q7*q7;
        }
#pragma unroll
        for (int off = 16; off > 0; off >>= 1) {
            s  += __shfl_xor_sync(0xFFFFFFFFu, s, off);
            sb += __shfl_xor_sync(0xFFFFFFFFu, sb, off);
        }
        if (lane == 0) {
            g_c2[n] = s;
            atomicMax(&g_mc2e,  encf(s));
            atomicMax(&g_mcb2e, encf(sb));
        }
        if (lane < 16) {
            uint4 w;
            w.x = packh(e0.x, e0.y);
            w.y = packh(e1.x, e1.y);
            w.z = packh(o0.x, o0.y);
            w.w = packh(o1.x, o1.y);
            g_bfrag[N][kt2][g * 4 + t] = w;
        }
    }
}

// ---------------------------------------------------------------------------
// sweep 1: single-plane fp16 GEMM; per (row, 16-center group) min(c2 - 2*dot)
// stored fp16 rounded DOWN. Single-chunk units (chunk-column-major ticket
// order keeps the B band L1/L2-hot chip-wide). GEMM body unchanged from R12;
// chunk processing stays straight-line (no unroll — R11 reg-ceiling lesson).
// ---------------------------------------------------------------------------
__global__ __launch_bounds__(128, 3)
void sweep1_kernel() {
    const int tid = threadIdx.x;
    const int w = tid >> 5, l = tid & 31;
    const int g = l >> 2, t = l & 3;
    const int mw = w >> 1, nw = w & 1;
    const uint4* __restrict__ Abase = &g_afrag[0][0][0];
    const uint4* __restrict__ Bbase = &g_bfrag[0][0][0];
    __shared__ int s_u;
    for (;;) {
        __syncthreads();
        if (tid == 0) s_u = atomicAdd(&g_t1, 1);
        __syncthreads();
        int u = s_u;
        if (u >= NUNITS) break;
        const int um = u & 511;            // 64-row block (fast axis)
        const int cc = u >> 9;             // chunk column (slow axis -> hot band)
        const int r0 = um * 64;
        const int mtb = um * 4 + mw * 2;
        const int tile0 = cc * 16 + nw * 8;

        float acc[2][8][4];
#pragma unroll
        for (int mt = 0; mt < 2; mt++)
#pragma unroll
            for (int nt = 0; nt < 8; nt++)
#pragma unroll
                for (int q = 0; q < 4; q++) acc[mt][nt][q] = 0.0f;

        const uint4* Ap = Abase + (size_t)mtb * 256 + l;
        const uint4* Bp = Bbase + (size_t)tile0 * 128 + l;
#pragma unroll
        for (int kt2 = 0; kt2 < 4; kt2++) {
            uint4 b4[8];
#pragma unroll
            for (int nt = 0; nt < 8; nt++) b4[nt] = __ldg(Bp + (size_t)nt * 128 + kt2 * 32);
            uint4 a0[2], a1[2];
#pragma unroll
            for (int mt = 0; mt < 2; mt++) a0[mt] = __ldg(Ap + (size_t)mt * 256 + (2 * kt2) * 32);
#pragma unroll
            for (int mt = 0; mt < 2; mt++) a1[mt] = __ldg(Ap + (size_t)mt * 256 + (2 * kt2 + 1) * 32);
#pragma unroll
            for (int mt = 0; mt < 2; mt++)
#pragma unroll
                for (int nt = 0; nt < 8; nt++)
                    mma16816(acc[mt][nt], a0[mt], b4[nt].x, b4[nt].y);
#pragma unroll
            for (int mt = 0; mt < 2; mt++)
#pragma unroll
                for (int nt = 0; nt < 8; nt++)
                    mma16816(acc[mt][nt], a1[mt], b4[nt].z, b4[nt].w);
        }

        // fold: per-row min of (c2 - 2*dot) per 16-center group
        float bv[4][4];
#pragma unroll
        for (int sl = 0; sl < 4; sl++)
#pragma unroll
            for (int gi = 0; gi < 4; gi++) bv[sl][gi] = INFINITY;
#pragma unroll
        for (int nt = 0; nt < 8; nt++) {
            int gi = nt >> 1;
            int col0 = (tile0 + nt) * 8 + 2 * t;
            float2 c2v = *reinterpret_cast<const float2*>(&g_c2[col0]);
#pragma unroll
            for (int mt = 0; mt < 2; mt++) {
                float m0 = fminf(c2v.x - 2.0f * acc[mt][nt][0], c2v.y - 2.0f * acc[mt][nt][1]);
                float m1 = fminf(c2v.x - 2.0f * acc[mt][nt][2], c2v.y - 2.0f * acc[mt][nt][3]);
                bv[mt*2+0][gi] = fminf(bv[mt*2+0][gi], m0);
                bv[mt*2+1][gi] = fminf(bv[mt*2+1][gi], m1);
            }
        }
#pragma unroll
        for (int sl = 0; sl < 4; sl++)
#pragma unroll
            for (int gi = 0; gi < 4; gi++) {
                bv[sl][gi] = fminf(bv[sl][gi], __shfl_xor_sync(0xFFFFFFFFu, bv[sl][gi], 1));
                bv[sl][gi] = fminf(bv[sl][gi], __shfl_xor_sync(0xFFFFFFFFu, bv[sl][gi], 2));
            }
        if (t == 0) {
            int grpbase = tile0 >> 1;      // multiple of 4
#pragma unroll
            for (int sl = 0; sl < 4; sl++) {
                int row = r0 + mw * 32 + (sl >> 1) * 16 + (sl & 1) * 8 + g;
                __half2 p0 = __halves2half2(__float2half_rd(bv[sl][0]), __float2half_rd(bv[sl][1]));
                __half2 p1 = __halves2half2(__float2half_rd(bv[sl][2]), __float2half_rd(bv[sl][3]));
                uint2 val;
                val.x = *reinterpret_cast<uint32_t*>(&p0);
                val.y = *reinterpret_cast<uint32_t*>(&p1);
                *reinterpret_cast<uint2*>(&g_smin16[row][grpbase]) = val;
            }
        }
    }
}

// ---------------------------------------------------------------------------
// phase 2: per-row threshold + exact fp32 rescan of flagged 16-groups + outputs
// Half-warp paired dots: lanes 0-15 reduce center c, lanes 16-31 reduce c+1.
// ---------------------------------------------------------------------------
__global__ __launch_bounds__(256)
void phase2_kernel(const float* __restrict__ x, const float* __restrict__ centers,
                   float* __restrict__ out) {
    const int tid = threadIdx.x;
    const int w = tid >> 5, l = tid & 31;
    const int row = blockIdx.x * 8 + w;

    const uint2* rm = reinterpret_cast<const uint2*>(&g_smin16[row][0]);  // 100 uint2
    uint2 u[4];
    u[0] = rm[l];
    u[1] = rm[l + 32];
    u[2] = rm[l + 64];
    u[3] = (l < 4) ? rm[l + 96] : make_uint2(0x7C007C00u, 0x7C007C00u);

    float4 v[4];
#pragma unroll
    for (int k = 0; k < 4; k++) {
        float2 f0 = __half22float2(*reinterpret_cast<__half2*>(&u[k].x));
        float2 f1 = __half22float2(*reinterpret_cast<__half2*>(&u[k].y));
        v[k] = make_float4(f0.x, f0.y, f1.x, f1.y);
    }

    float m = INFINITY;
#pragma unroll
    for (int k = 0; k < 4; k++)
        m = fminf(m, fminf(fminf(v[k].x, v[k].y), fminf(v[k].z, v[k].w)));
#pragma unroll
    for (int off = 16; off > 0; off >>= 1)
        m = fminf(m, __shfl_xor_sync(0xFFFFFFFFu, m, off));

    const float x2 = g_x2[row];
    const float xn = sqrtf(x2), xbn = sqrtf(g_xb2[row]);
    const float cn = sqrtf(decf(g_mc2e)), cbn = sqrtf(decf(g_mcb2e));
    const float E = xbn * cn + xn * cbn + xbn * cbn + 2e-6f * xn * cn;
    const float th = m + 4.0f * E + 6e-3f;   // +2e-3 slack for fp16 round-down table

    unsigned f = 0;
#pragma unroll
    for (int k = 0; k < 4; k++) {
        unsigned nib = (v[k].x <= th ? 1u : 0u) | (v[k].y <= th ? 2u : 0u)
                     | (v[k].z <= th ? 4u : 0u) | (v[k].w <= th ? 8u : 0u);
        f |= nib << (4 * k);
    }

    // half-warp pairing: lanes 0-15 handle even candidate, 16-31 odd
    const int hl = l & 15;      // half-lane
    const int hs = l >> 4;      // half select
    const float4* x4 = reinterpret_cast<const float4*>(x + (size_t)row * DIM);
    const float4 xa = x4[hl];
    const float4 xb = x4[hl + 16];

    float bestv = INFINITY;
    int   besti = 0;

    unsigned mask = __ballot_sync(0xFFFFFFFFu, f != 0);
    while (mask) {
        int src = __ffs(mask) - 1;
        mask &= mask - 1;
        unsigned fs = __shfl_sync(0xFFFFFFFFu, f, src);
        while (fs) {
            int b = __ffs(fs) - 1;
            fs &= fs - 1;
            int k = b >> 2, j = b & 3;
            int grp = (src + 32 * k) * 4 + j;
            int cbase = grp * 16;
#pragma unroll 2
            for (int i = 0; i < 16; i += 2) {
                int c = cbase + i + hs;
                const float4* c4 = reinterpret_cast<const float4*>(centers + (size_t)c * DIM);
                float4 ca = c4[hl];
                float4 cb = c4[hl + 16];
                float p = xa.x * ca.x;
                p = fmaf(xa.y, ca.y, p);
                p = fmaf(xa.z, ca.z, p);
                p = fmaf(xa.w, ca.w, p);
                p = fmaf(xb.x, cb.x, p);
                p = fmaf(xb.y, cb.y, p);
                p = fmaf(xb.z, cb.z, p);
                p = fmaf(xb.w, cb.w, p);
#pragma unroll
                for (int off = 8; off > 0; off >>= 1)
                    p += __shfl_xor_sync(0xFFFFFFFFu, p, off);
                if (hl == 0) {
                    float sq = (x2 + g_c2[c]) - 2.0f * p;
                    if (sq < bestv || (sq == bestv && c < besti)) { bestv = sq; besti = c; }
                }
            }
        }
    }

    // final (value, index) reduce across warp — deterministic first-index tie-break
#pragma unroll
    for (int off = 16; off > 0; off >>= 1) {
        float ov = __shfl_xor_sync(0xFFFFFFFFu, bestv, off);
        int   oi = __shfl_xor_sync(0xFFFFFFFFu, besti, off);
        if (ov < bestv || (ov == bestv && oi < besti)) { bestv = ov; besti = oi; }
    }

    if (l == 0) {
        float* outAssign = out + (size_t)BATCH * DIM;
        float* outDist   = outAssign + BATCH;
        float* outClass  = outDist + BATCH;
        outAssign[row] = (float)(besti % KC);
        outDist[row]   = sqrtf(fmaxf(bestv, 0.0f));
        outClass[row]  = (float)(besti / KC);
    }
    float4 cbv = reinterpret_cast<const float4*>(centers)[(size_t)besti * 32 + l];
    reinterpret_cast<float4*>(out)[(size_t)row * 32 + l] = cbv;
}

extern "C" void kernel_launch(void* const* d_in, const int* in_sizes, int n_in,
                              void* d_out, int out_size) {
    const float* x       = (const float*)d_in[0];
    const float* centers = (const float*)d_in[1];
    float* out = (float*)d_out;

    prep_kernel<<<((BATCH + NCENT) * 32 + 255) / 256, 256>>>(x, centers);
    sweep1_kernel<<<GRID_SW, 128>>>();
    phase2_kernel<<<BATCH / 8, 256>>>(x, centers, out);
}

// round 14
// speedup vs baseline: 1.0999x; 1.0999x over previous
#include <cuda_runtime.h>
#include <cuda_fp16.h>
#include <math.h>
#include <stdint.h>

// ---------------- problem constants ----------------
#define BATCH     32768
#define DIM       128
#define NCENT     6400
#define KC        64
#define AMT       (BATCH / 16)     // 2048 A row-tiles (m16)
#define BNT       (NCENT / 8)      // 800  B col-tiles (n8)
#define NSLICES   10
#define NSLC_T    80               // n8-tiles per slice (640 centers)
#define NUNITS    (512 * NSLICES)  // 5120 units (5 chunks each) — R12 granularity
#define NGRP      400              // 16-center groups
#define GRID_SW   444              // 148 SMs x occ 3

// ---------------- device scratch ----------------
__device__ uint4 g_afrag[AMT][8][32];      // 8.4 MB (fp16 main plane, A frag)
__device__ uint4 g_bfrag[BNT][4][32];      // 1.6 MB (fp16 main plane, B frag, kt-pair)
__device__ float g_c2[NCENT];
__device__ float g_x2[BATCH];
__device__ float g_xb2[BATCH];             // ||x - fp16(x)||^2
__device__ __half g_smin16[BATCH][NGRP];   // 26 MB: per (row, 16-group) min, rounded DOWN
__device__ int   g_t1;
__device__ unsigned g_mc2e, g_mcb2e;       // enc(max c2), enc(max ||c_res||^2); idempotent

// ---------------- helpers ----------------
__device__ __forceinline__ uint32_t packh(float lo, float hi) {
    __half2 h = __floats2half2_rn(lo, hi);
    return *reinterpret_cast<uint32_t*>(&h);
}
__device__ __forceinline__ float h16(float v) { return __half2float(__float2half_rn(v)); }
__device__ __forceinline__ uint32_t encf(float f) {
    uint32_t u = __float_as_uint(f);
    return (u & 0x80000000u) ? ~u : (u | 0x80000000u);
}
__device__ __forceinline__ float decf(uint32_t e) {
    uint32_t u = (e & 0x80000000u) ? (e ^ 0x80000000u) : ~e;
    return __uint_as_float(u);
}
__device__ __forceinline__ void mma16816(float* d, const uint4& a,
                                         uint32_t b0, uint32_t b1) {
    asm volatile(
        "mma.sync.aligned.m16n8k16.row.col.f32.f16.f16.f32 "
        "{%0,%1,%2,%3}, {%4,%5,%6,%7}, {%8,%9}, {%0,%1,%2,%3};"
        : "+f"(d[0]), "+f"(d[1]), "+f"(d[2]), "+f"(d[3])
        : "r"(a.x), "r"(a.y), "r"(a.z), "r"(a.w), "r"(b0), "r"(b1));
}

// ---------------------------------------------------------------------------
// merged prep: warps [0, BATCH) -> x rows; warps [BATCH, BATCH+NCENT) -> centers
// ---------------------------------------------------------------------------
__global__ void prep_kernel(const float* __restrict__ x,
                            const float* __restrict__ centers) {
    int warp = (blockIdx.x * blockDim.x + threadIdx.x) >> 5;
    int lane = threadIdx.x & 31;

    if (warp < BATCH) {
        int r = warp;
        int M = r >> 4, g = r & 15;
        int kt = lane >> 2, t = lane & 3;
        const float* row = x + (size_t)r * DIM;
        float2 lo = *reinterpret_cast<const float2*>(row + kt * 16 + 2 * t);
        float2 hi = *reinterpret_cast<const float2*>(row + kt * 16 + 8 + 2 * t);

        float r0 = lo.x - h16(lo.x), r1 = lo.y - h16(lo.y);
        float r2 = hi.x - h16(hi.x), r3 = hi.y - h16(hi.y);
        float s  = lo.x * lo.x + lo.y * lo.y + hi.x * hi.x + hi.y * hi.y;
        float sb = r0 * r0 + r1 * r1 + r2 * r2 + r3 * r3;
#pragma unroll
        for (int off = 16; off > 0; off >>= 1) {
            s  += __shfl_xor_sync(0xFFFFFFFFu, s, off);
            sb += __shfl_xor_sync(0xFFFFFFFFu, sb, off);
        }
        if (lane == 0) { g_x2[r] = s; g_xb2[r] = sb; }
        if (warp == 0 && lane == 1) g_t1 = 0;

        uint32_t w0 = packh(lo.x, lo.y);
        uint32_t w1 = packh(hi.x, hi.y);
        uint32_t* base = reinterpret_cast<uint32_t*>(&g_afrag[M][kt][(g & 7) * 4 + t]);
        if (g < 8) { base[0] = w0; base[2] = w1; }
        else       { base[1] = w0; base[3] = w1; }
    } else if (warp < BATCH + NCENT) {
        int n = warp - BATCH;
        int N = n >> 3, g = n & 7;
        int j = lane & 15;
        int kt2 = j >> 2, t = j & 3;
        const float* row = centers + (size_t)n * DIM;
        int c0 = kt2 * 32 + 2 * t;
        float2 e0, e1, o0, o1;
        float s = 0.0f, sb = 0.0f;
        if (lane < 16) {
            e0 = *reinterpret_cast<const float2*>(row + c0);
            e1 = *reinterpret_cast<const float2*>(row + c0 + 8);
            o0 = *reinterpret_cast<const float2*>(row + c0 + 16);
            o1 = *reinterpret_cast<const float2*>(row + c0 + 24);
            float q0 = e0.x - h16(e0.x), q1 = e0.y - h16(e0.y);
            float q2 = e1.x - h16(e1.x), q3 = e1.y - h16(e1.y);
            float q4 = o0.x - h16(o0.x), q5 = o0.y - h16(o0.y);
            float q6 = o1.x - h16(o1.x), q7 = o1.y - h16(o1.y);
            s  = e0.x*e0.x + e0.y*e0.y + e1.x*e1.x + e1.y*e1.y
               + o0.x*o0.x + o0.y*o0.y + o1.x*o1.x + o1.y*o1.y;
            sb = q0*q0 + q1*q1 + q2*q2 + q3*q3 + q4*q4 + q5*q5 + q6*q6 + q7*q7;
        }
#pragma unroll
        for (int off = 16; off > 0; off >>= 1) {
            s  += __shfl_xor_sync(0xFFFFFFFFu, s, off);
            sb += __shfl_xor_sync(0xFFFFFFFFu, sb, off);
        }
        if (lane == 0) {
            g_c2[n] = s;
            atomicMax(&g_mc2e,  encf(s));
            atomicMax(&g_mcb2e, encf(sb));
        }
        if (lane < 16) {
            uint4 w;
            w.x = packh(e0.x, e0.y);
            w.y = packh(e1.x, e1.y);
            w.z = packh(o0.x, o0.y);
            w.w = packh(o1.x, o1.y);
            g_bfrag[N][kt2][g * 4 + t] = w;
        }
    }
}

// ---------------------------------------------------------------------------
// sweep 1 (R12 body): single-plane fp16 GEMM; per (row, 16-group) min stored
// fp16 rounded DOWN. 5-chunk units (ticket overhead ~1.6% — R13 showed
// finer units regress). Chunk loop stays unroll 1 (R11 reg-ceiling lesson).
// ---------------------------------------------------------------------------
__global__ __launch_bounds__(128, 3)
void sweep1_kernel() {
    const int tid = threadIdx.x;
    const int w = tid >> 5, l = tid & 31;
    const int g = l >> 2, t = l & 3;
    const int mw = w >> 1, nw = w & 1;
    const uint4* __restrict__ Abase = &g_afrag[0][0][0];
    const uint4* __restrict__ Bbase = &g_bfrag[0][0][0];
    __shared__ int s_u;
    for (;;) {
        __syncthreads();
        if (tid == 0) s_u = atomicAdd(&g_t1, 1);
        __syncthreads();
        int u = s_u;
        if (u >= NUNITS) break;
        const int um = u & 511, s = u >> 9;
        const int r0 = um * 64;
        const int mtb = um * 4 + mw * 2;
        const int tbase = s * NSLC_T;

#pragma unroll 1
        for (int ch = 0; ch < 5; ch++) {
            const int tile0 = tbase + ch * 16 + nw * 8;
            float acc[2][8][4];
#pragma unroll
            for (int mt = 0; mt < 2; mt++)
#pragma unroll
                for (int nt = 0; nt < 8; nt++)
#pragma unroll
                    for (int q = 0; q < 4; q++) acc[mt][nt][q] = 0.0f;

            const uint4* Ap = Abase + (size_t)mtb * 256 + l;
            const uint4* Bp = Bbase + (size_t)tile0 * 128 + l;
#pragma unroll
            for (int kt2 = 0; kt2 < 4; kt2++) {
                uint4 b4[8];
#pragma unroll
                for (int nt = 0; nt < 8; nt++) b4[nt] = __ldg(Bp + (size_t)nt * 128 + kt2 * 32);
                uint4 a0[2], a1[2];
#pragma unroll
                for (int mt = 0; mt < 2; mt++) a0[mt] = __ldg(Ap + (size_t)mt * 256 + (2 * kt2) * 32);
#pragma unroll
                for (int mt = 0; mt < 2; mt++) a1[mt] = __ldg(Ap + (size_t)mt * 256 + (2 * kt2 + 1) * 32);
#pragma unroll
                for (int mt = 0; mt < 2; mt++)
#pragma unroll
                    for (int nt = 0; nt < 8; nt++)
                        mma16816(acc[mt][nt], a0[mt], b4[nt].x, b4[nt].y);
#pragma unroll
                for (int mt = 0; mt < 2; mt++)
#pragma unroll
                    for (int nt = 0; nt < 8; nt++)
                        mma16816(acc[mt][nt], a1[mt], b4[nt].z, b4[nt].w);
            }

            // fold: per-row min of (c2 - 2*dot) per 16-center group
            float bv[4][4];
#pragma unroll
            for (int sl = 0; sl < 4; sl++)
#pragma unroll
                for (int gi = 0; gi < 4; gi++) bv[sl][gi] = INFINITY;
#pragma unroll
            for (int nt = 0; nt < 8; nt++) {
                int gi = nt >> 1;
                int col0 = (tile0 + nt) * 8 + 2 * t;
                float2 c2v = *reinterpret_cast<const float2*>(&g_c2[col0]);
#pragma unroll
                for (int mt = 0; mt < 2; mt++) {
                    float m0 = fminf(c2v.x - 2.0f * acc[mt][nt][0], c2v.y - 2.0f * acc[mt][nt][1]);
                    float m1 = fminf(c2v.x - 2.0f * acc[mt][nt][2], c2v.y - 2.0f * acc[mt][nt][3]);
                    bv[mt*2+0][gi] = fminf(bv[mt*2+0][gi], m0);
                    bv[mt*2+1][gi] = fminf(bv[mt*2+1][gi], m1);
                }
            }
#pragma unroll
            for (int sl = 0; sl < 4; sl++)
#pragma unroll
                for (int gi = 0; gi < 4; gi++) {
                    bv[sl][gi] = fminf(bv[sl][gi], __shfl_xor_sync(0xFFFFFFFFu, bv[sl][gi], 1));
                    bv[sl][gi] = fminf(bv[sl][gi], __shfl_xor_sync(0xFFFFFFFFu, bv[sl][gi], 2));
                }
            if (t == 0) {
                int grpbase = tile0 >> 1;      // multiple of 4
#pragma unroll
                for (int sl = 0; sl < 4; sl++) {
                    int row = r0 + mw * 32 + (sl >> 1) * 16 + (sl & 1) * 8 + g;
                    __half2 p0 = __halves2half2(__float2half_rd(bv[sl][0]), __float2half_rd(bv[sl][1]));
                    __half2 p1 = __halves2half2(__float2half_rd(bv[sl][2]), __float2half_rd(bv[sl][3]));
                    uint2 val;
                    val.x = *reinterpret_cast<uint32_t*>(&p0);
                    val.y = *reinterpret_cast<uint32_t*>(&p1);
                    *reinterpret_cast<uint2*>(&g_smin16[row][grpbase]) = val;
                }
            }
        }
    }
}

// ---------------------------------------------------------------------------
// phase 2 (R13 body): threshold + exact fp32 rescan, half-warp paired dots.
// ---------------------------------------------------------------------------
__global__ __launch_bounds__(256)
void phase2_kernel(const float* __restrict__ x, const float* __restrict__ centers,
                   float* __restrict__ out) {
    const int tid = threadIdx.x;
    const int w = tid >> 5, l = tid & 31;
    const int row = blockIdx.x * 8 + w;

    const uint2* rm = reinterpret_cast<const uint2*>(&g_smin16[row][0]);  // 100 uint2
    uint2 u[4];
    u[0] = rm[l];
    u[1] = rm[l + 32];
    u[2] = rm[l + 64];
    u[3] = (l < 4) ? rm[l + 96] : make_uint2(0x7C007C00u, 0x7C007C00u);

    float4 v[4];
#pragma unroll
    for (int k = 0; k < 4; k++) {
        float2 f0 = __half22float2(*reinterpret_cast<__half2*>(&u[k].x));
        float2 f1 = __half22float2(*reinterpret_cast<__half2*>(&u[k].y));
        v[k] = make_float4(f0.x, f0.y, f1.x, f1.y);
    }

    float m = INFINITY;
#pragma unroll
    for (int k = 0; k < 4; k++)
        m = fminf(m, fminf(fminf(v[k].x, v[k].y), fminf(v[k].z, v[k].w)));
#pragma unroll
    for (int off = 16; off > 0; off >>= 1)
        m = fminf(m, __shfl_xor_sync(0xFFFFFFFFu, m, off));

    const float x2 = g_x2[row];
    const float xn = sqrtf(x2), xbn = sqrtf(g_xb2[row]);
    const float cn = sqrtf(decf(g_mc2e)), cbn = sqrtf(decf(g_mcb2e));
    const float E = xbn * cn + xn * cbn + xbn * cbn + 2e-6f * xn * cn;
    const float th = m + 4.0f * E + 6e-3f;   // +2e-3 slack for fp16 round-down table

    unsigned f = 0;
#pragma unroll
    for (int k = 0; k < 4; k++) {
        unsigned nib = (v[k].x <= th ? 1u : 0u) | (v[k].y <= th ? 2u : 0u)
                     | (v[k].z <= th ? 4u : 0u) | (v[k].w <= th ? 8u : 0u);
        f |= nib << (4 * k);
    }

    // half-warp pairing: lanes 0-15 handle even candidate, 16-31 odd
    const int hl = l & 15;      // half-lane
    const int hs = l >> 4;      // half select
    const float4* x4 = reinterpret_cast<const float4*>(x + (size_t)row * DIM);
    const float4 xa = x4[hl];
    const float4 xb = x4[hl + 16];

    float bestv = INFINITY;
    int   besti = 0;

    unsigned mask = __ballot_sync(0xFFFFFFFFu, f != 0);
    while (mask) {
        int src = __ffs(mask) - 1;
        mask &= mask - 1;
        unsigned fs = __shfl_sync(0xFFFFFFFFu, f, src);
        while (fs) {
            int b = __ffs(fs) - 1;
            fs &= fs - 1;
            int k = b >> 2, j = b & 3;
            int grp = (src + 32 * k) * 4 + j;
            int cbase = grp * 16;
#pragma unroll 2
            for (int i = 0; i < 16; i += 2) {
                int c = cbase + i + hs;
                const float4* c4 = reinterpret_cast<const float4*>(centers + (size_t)c * DIM);
                float4 ca = c4[hl];
                float4 cb = c4[hl + 16];
                float p = xa.x * ca.x;
                p = fmaf(xa.y, ca.y, p);
                p = fmaf(xa.z, ca.z, p);
                p = fmaf(xa.w, ca.w, p);
                p = fmaf(xb.x, cb.x, p);
                p = fmaf(xb.y, cb.y, p);
                p = fmaf(xb.z, cb.z, p);
                p = fmaf(xb.w, cb.w, p);
#pragma unroll
                for (int off = 8; off > 0; off >>= 1)
                    p += __shfl_xor_sync(0xFFFFFFFFu, p, off);
                if (hl == 0) {
                    float sq = (x2 + g_c2[c]) - 2.0f * p;
                    if (sq < bestv || (sq == bestv && c < besti)) { bestv = sq; besti = c; }
                }
            }
        }
    }

    // final (value, index) reduce across warp — deterministic first-index tie-break
#pragma unroll
    for (int off = 16; off > 0; off >>= 1) {
        float ov = __shfl_xor_sync(0xFFFFFFFFu, bestv, off);
        int   oi = __shfl_xor_sync(0xFFFFFFFFu, besti, off);
        if (ov < bestv || (ov == bestv && oi < besti)) { bestv = ov; besti = oi; }
    }

    if (l == 0) {
        float* outAssign = out + (size_t)BATCH * DIM;
        float* outDist   = outAssign + BATCH;
        float* outClass  = outDist + BATCH;
        outAssign[row] = (float)(besti % KC);
        outDist[row]   = sqrtf(fmaxf(bestv, 0.0f));
        outClass[row]  = (float)(besti / KC);
    }
    float4 cbv = reinterpret_cast<const float4*>(centers)[(size_t)besti * 32 + l];
    reinterpret_cast<float4*>(out)[(size_t)row * 32 + l] = cbv;
}

extern "C" void kernel_launch(void* const* d_in, const int* in_sizes, int n_in,
                              void* d_out, int out_size) {
    const float* x       = (const float*)d_in[0];
    const float* centers = (const float*)d_in[1];
    float* out = (float*)d_out;

    prep_kernel<<<((BATCH + NCENT) * 32 + 255) / 256, 256>>>(x, centers);
    sweep1_kernel<<<GRID_SW, 128>>>();
    phase2_kernel<<<BATCH / 8, 256>>>(x, centers, out);
}